// round 16
// baseline (speedup 1.0000x reference)
#include <cuda_runtime.h>
#include <cuda_fp16.h>
#include <cuda_bf16.h>
#include <cstdint>

// Fused SIREN MLP via single-product fp16 HMMA: 3 -> 256 -> 256 -> 256 -> 256 -> 3
// Round 15:
//  (1) layer 0 folded into the MMA chunk stream: one K=16 MMA with split
//      operands  A0=[xh,xh,xl,1], B0=30*[wh,wl,wh,b]  (z0 exact to ~1e-6),
//      prep kernel emits B0 as chunk t=0 in the standard layout.
//  (2) epilogue sins computed into registers BEFORE the mw-group barrier;
//      the barM..barM critical section is STS-only.
// Rest as R14: 2 CTAs/SM, per-nw-pair B staging + named barriers, packed
// f32x2 sin math, static activation scaling S={1,16,512}.

#define NTHREADS 256
#define PTILE 64
#define HID 256
#define AROWB 528
#define BROWB 80

#define OFF_B    33792
#define BG       5120      // one buf for one nw-group: 64 rows x 80B
#define OFF_PSUM 74752
#define OFF_XS   77824
#define SMEM_SZ  78592

#define PREP_C   20480
#define NT_TOTAL 25        // t=0: layer0 B0; t=1..24: 3 layers x 8 chunks

typedef unsigned long long ull;

__device__ __align__(16) unsigned char g_prepW[NT_TOTAL * PREP_C];

__device__ __forceinline__ uint32_t smem_u32(const void* p) {
    uint32_t a;
    asm("{ .reg .u64 t; cvta.to.shared.u64 t, %1; cvt.u32.u64 %0, t; }"
        : "=r"(a) : "l"(p));
    return a;
}

#define BAR_SYNC(id, n) \
    asm volatile("bar.sync %0, %1;" :: "r"(id), "r"(n) : "memory")

__device__ __forceinline__ void ldsm4(uint32_t a[4], uint32_t addr) {
    asm volatile("ldmatrix.sync.aligned.m8n8.x4.shared.b16 {%0,%1,%2,%3}, [%4];"
                 : "=r"(a[0]), "=r"(a[1]), "=r"(a[2]), "=r"(a[3]) : "r"(addr));
}

__device__ __forceinline__ void mma16816(float d[4], const uint32_t a[4],
                                         uint32_t b0, uint32_t b1) {
    asm volatile("mma.sync.aligned.m16n8k16.row.col.f32.f16.f16.f32 "
                 "{%0,%1,%2,%3}, {%4,%5,%6,%7}, {%8,%9}, {%0,%1,%2,%3};"
                 : "+f"(d[0]), "+f"(d[1]), "+f"(d[2]), "+f"(d[3])
                 : "r"(a[0]), "r"(a[1]), "r"(a[2]), "r"(a[3]),
                   "r"(b0), "r"(b1));
}

__device__ __forceinline__ void cpa16(uint32_t dst, const void* src) {
    asm volatile("cp.async.cg.shared.global [%0], [%1], 16;"
                 :: "r"(dst), "l"(src) : "memory");
}
#define CP_COMMIT() asm volatile("cp.async.commit_group;" ::: "memory")
#define CP_WAIT0()  asm volatile("cp.async.wait_group 0;" ::: "memory")

// ---------------- packed f32x2 helpers ----------------
__device__ __forceinline__ ull fma2(ull a, ull b, ull c) {
    ull d;
    asm("fma.rn.f32x2 %0, %1, %2, %3;" : "=l"(d) : "l"(a), "l"(b), "l"(c));
    return d;
}
__device__ __forceinline__ ull mul2(ull a, ull b) {
    ull d;
    asm("mul.rn.f32x2 %0, %1, %2;" : "=l"(d) : "l"(a), "l"(b));
    return d;
}
__device__ __forceinline__ ull add2(ull a, ull b) {
    ull d;
    asm("add.rn.f32x2 %0, %1, %2;" : "=l"(d) : "l"(a), "l"(b));
    return d;
}
__device__ __forceinline__ ull pack2f(float lo, float hi) {
    ull d;
    asm("mov.b64 %0, {%1, %2};" : "=l"(d) : "f"(lo), "f"(hi));
    return d;
}
__device__ __forceinline__ void unpack2f(ull v, float& lo, float& hi) {
    asm("mov.b64 {%0, %1}, %2;" : "=f"(lo), "=f"(hi) : "l"(v));
}
__device__ __forceinline__ uint32_t packh(float v0, float v1) {
    uint32_t r;
    asm("cvt.rn.f16x2.f32 %0, %1, %2;" : "=r"(r) : "f"(v1), "f"(v0));
    return r;
}
__device__ __forceinline__ uint32_t cvt2h(ull v) {
    float lo, hi;
    unpack2f(v, lo, hi);
    return packh(lo, hi);
}

// packed sin for |x| <= pi/2
__device__ __forceinline__ ull sin2_small(ull x) {
    const ull C3 = pack2f(-1.6666667e-1f, -1.6666667e-1f);
    const ull C5 = pack2f( 8.3333310e-3f,  8.3333310e-3f);
    const ull C7 = pack2f(-1.9841271e-4f, -1.9841271e-4f);
    const ull C9 = pack2f( 2.7557314e-6f,  2.7557314e-6f);
    ull x2 = mul2(x, x);
    ull x3 = mul2(x2, x);
    ull p = fma2(C9, x2, C7);
    p = fma2(p, x2, C5);
    p = fma2(p, x2, C3);
    return fma2(p, x3, x);
}

// packed accurate sin for |z| <= ~32 (magic-number rint + Cody-Waite by pi)
__device__ __forceinline__ ull sin2_cw(ull z) {
    const ull INVPI = pack2f(0.318309886183790672f, 0.318309886183790672f);
    const ull MAG   = pack2f(12582912.0f, 12582912.0f);
    const ull NMAG  = pack2f(-12582912.0f, -12582912.0f);
    const ull NPIH  = pack2f(-3.14159274101257324f, -3.14159274101257324f);
    const ull PILO  = pack2f(8.74227800296169792e-8f, 8.74227800296169792e-8f);
    ull t = fma2(z, INVPI, MAG);
    ull sgn = ((t & 1ull) << 31) | (((t >> 32) & 1ull) << 63);
    ull k = add2(t, NMAG);
    ull r = fma2(k, NPIH, z);
    r = fma2(k, PILO, r);
    return sin2_small(r) ^ sgn;
}

// ---- prep: weights -> fp16 chunk-contiguous; chunk 0 = layer-0 B0 ----
__global__ void siren_prep_kernel(const float* __restrict__ W0,
                                  const float* __restrict__ b0,
                                  const float* __restrict__ W1,
                                  const float* __restrict__ W2,
                                  const float* __restrict__ W3) {
    int idx = blockIdx.x * blockDim.x + threadIdx.x;
    if (idx < 3 * 256 * 128) {
        int L = idx / (256 * 128);
        int r = idx % (256 * 128);
        int n = r / 128;
        int k = (r % 128) * 2;
        const float* W = (L == 0) ? W1 : (L == 1) ? W2 : W3;
        float v0 = __ldg(W + n * HID + k);
        float v1 = __ldg(W + n * HID + k + 1);
        unsigned char* dst = g_prepW + (1 + L * 8 + (k >> 5)) * PREP_C
                           + n * BROWB + (k & 31) * 2;
        *(uint32_t*)dst = packh(v0, v1);
    }
    if (idx < 256) {
        // B0 row n: 30*[wh0,wh1,wh2, wl0,wl1,wl2, wh0,wh1 | wh2, b, 0...]
        int n = idx;
        float w0 = 30.0f * __ldg(W0 + n * 3);
        float w1 = 30.0f * __ldg(W0 + n * 3 + 1);
        float w2 = 30.0f * __ldg(W0 + n * 3 + 2);
        float bb = 30.0f * __ldg(b0 + n);
        __half h0 = __float2half(w0), h1 = __float2half(w1), h2 = __float2half(w2);
        __half l0 = __float2half(w0 - __half2float(h0));
        __half l1 = __float2half(w1 - __half2float(h1));
        __half l2 = __float2half(w2 - __half2float(h2));
        __half hb = __float2half(bb);
        __half row[16];
        row[0] = h0; row[1] = h1; row[2] = h2;
        row[3] = l0; row[4] = l1; row[5] = l2;
        row[6] = h0; row[7] = h1;
        row[8] = h2; row[9] = hb;
#pragma unroll
        for (int i = 10; i < 16; i++) row[i] = __float2half(0.0f);
        unsigned char* dst = g_prepW + n * BROWB;
        *(uint4*)dst = *(uint4*)row;
        *(uint4*)(dst + 16) = *(uint4*)(row + 8);
    }
}

__global__ void __launch_bounds__(NTHREADS, 2) siren_mma_kernel(
    const float* __restrict__ x,
    const float* __restrict__ b1, const float* __restrict__ b2,
    const float* __restrict__ b3,
    const float* __restrict__ W4, const float* __restrict__ b4,
    float* __restrict__ out, int npts)
{
    extern __shared__ char smem[];
    const uint32_t sb = smem_u32(smem);
    const int tid = threadIdx.x;
    const int w = tid >> 5, l = tid & 31;
    const int mw = w & 1, nw = w >> 1;       // 2 M-groups x 4 N-groups
    const int tile0 = blockIdx.x * PTILE;

    float* xs = (float*)(smem + OFF_XS);
    float* psum = (float*)(smem + OFF_PSUM);

    const uint32_t stBase = sb + OFF_B + (uint32_t)(nw * 2 * BG + mw * 2560
                                                    + l * 16);
    const uint32_t prepWoff = (uint32_t)(nw * BG + mw * 2560 + l * 16);

    if (tid < PTILE * 3) {
        int idx = tile0 * 3 + tid;
        xs[tid] = (idx < npts * 3) ? x[idx] : 0.0f;
    }

    // prefetch chunk 0 (layer-0 B0) immediately
    {
        const unsigned char* src = g_prepW + prepWoff;
#pragma unroll
        for (int i = 0; i < 5; i++)
            cpa16(stBase + i * 512, src + i * 512);
        CP_COMMIT();
    }
    __syncthreads();                         // xs visible

    // ---- stage A0: row p = [xh,xh,xl,1] fp16 (split input) ----
    if (tid < PTILE) {
        int p = tid;
        float x0 = xs[p * 3], x1 = xs[p * 3 + 1], x2 = xs[p * 3 + 2];
        __half h0 = __float2half(x0), h1 = __float2half(x1), h2 = __float2half(x2);
        __half l0 = __float2half(x0 - __half2float(h0));
        __half l1 = __float2half(x1 - __half2float(h1));
        __half l2 = __float2half(x2 - __half2float(h2));
        __half row[16];
        row[0] = h0; row[1] = h1; row[2] = h2;
        row[3] = h0; row[4] = h1; row[5] = h2;
        row[6] = l0; row[7] = l1;
        row[8] = l2; row[9] = __float2half(1.0f);
#pragma unroll
        for (int i = 10; i < 16; i++) row[i] = __float2half(0.0f);
        *(uint4*)(smem + p * AROWB) = *(uint4*)row;
        *(uint4*)(smem + p * AROWB + 16) = *(uint4*)(row + 8);
    }
    __syncthreads();                         // A0 visible

    // ---- ldmatrix per-lane addresses ----
    const int lt = l >> 3, l7 = l & 7;
    const uint32_t aBase = sb + (uint32_t)((mw * 32 + l7 + ((lt & 1) << 3)) * AROWB
                                           + (((lt >> 1) << 3) * 2));
    const uint32_t bBase = sb + OFF_B + (uint32_t)(nw * 2 * BG
        + (l7 + ((lt >> 1) << 3)) * BROWB + (((lt & 1) << 3) * 2));

    const int barPair = 1 + nw;
    const int barM = 5 + mw;

    float acc[2][8][4];
#pragma unroll
    for (int mt = 0; mt < 2; mt++)
#pragma unroll
        for (int nt = 0; nt < 8; nt++)
#pragma unroll
            for (int q = 0; q < 4; q++) acc[mt][nt][q] = 0.0f;

    float part[2][2][3];
#pragma unroll
    for (int mt = 0; mt < 2; mt++)
#pragma unroll
        for (int rh = 0; rh < 2; rh++)
#pragma unroll
            for (int cc = 0; cc < 3; cc++) part[mt][rh][cc] = 0.0f;

#pragma unroll 1
    for (int t = 0; t < NT_TOTAL; t++) {
        CP_WAIT0();
        BAR_SYNC(barPair, 64);               // chunk t staged, old buf free

        if (t + 1 < NT_TOTAL) {
            const unsigned char* src = g_prepW + (t + 1) * PREP_C + prepWoff;
            uint32_t dst = stBase + (uint32_t)(((t + 1) & 1) * BG);
#pragma unroll
            for (int i = 0; i < 5; i++)
                cpa16(dst + i * 512, src + i * 512);
            CP_COMMIT();
        }

        const uint32_t bufB = bBase + (uint32_t)((t & 1) * BG);
        const int nsteps = (t == 0) ? 1 : 2;
        const int cbase = (t == 0) ? 0 : ((t - 1) & 7) * 2;
#pragma unroll 1
        for (int s = 0; s < nsteps; s++) {
            const int kk = cbase + s;
            uint32_t af[2][4];
            ldsm4(af[0], aBase + kk * 32);
            ldsm4(af[1], aBase + 16 * AROWB + kk * 32);
#pragma unroll
            for (int np = 0; np < 4; np++) {
                uint32_t bf[4];
                ldsm4(bf, bufB + np * 16 * BROWB + s * 32);
                mma16816(acc[0][2 * np],     af[0], bf[0], bf[1]);
                mma16816(acc[1][2 * np],     af[1], bf[0], bf[1]);
                mma16816(acc[0][2 * np + 1], af[0], bf[2], bf[3]);
                mma16816(acc[1][2 * np + 1], af[1], bf[2], bf[3]);
            }
        }

        // ---- layer boundaries: t = 0, 8, 16, 24 ----
        if (t == 0 || ((t - 1) & 7) == 7) {
            if (t < 24) {
                // pre-barrier: sins into registers (overwrite acc)
                if (t == 0) {
#pragma unroll
                    for (int mt = 0; mt < 2; mt++)
#pragma unroll
                    for (int nt = 0; nt < 8; nt++) {
                        ull z01 = pack2f(acc[mt][nt][0], acc[mt][nt][1]);
                        ull z23 = pack2f(acc[mt][nt][2], acc[mt][nt][3]);
                        acc[mt][nt][0] = __uint_as_float(cvt2h(sin2_cw(z01)));
                        acc[mt][nt][1] = __uint_as_float(cvt2h(sin2_cw(z23)));
                    }
                } else {
                    const float* bb = (t == 8) ? b1 : b2;
                    const ull is2 = (t == 8) ? pack2f(1.0f, 1.0f)
                                             : pack2f(1.0f/16.0f, 1.0f/16.0f);
                    const ull so2 = (t == 8) ? pack2f(16.0f, 16.0f)
                                             : pack2f(512.0f, 512.0f);
#pragma unroll
                    for (int mt = 0; mt < 2; mt++)
#pragma unroll
                    for (int nt = 0; nt < 8; nt++) {
                        int nc = nw * 64 + nt * 8 + (l & 3) * 2;
                        float2 bp = __ldg(reinterpret_cast<const float2*>(bb + nc));
                        ull b2p = pack2f(bp.x, bp.y);
                        ull z01 = fma2(pack2f(acc[mt][nt][0], acc[mt][nt][1]),
                                       is2, b2p);
                        ull z23 = fma2(pack2f(acc[mt][nt][2], acc[mt][nt][3]),
                                       is2, b2p);
                        acc[mt][nt][0] = __uint_as_float(
                            cvt2h(mul2(sin2_small(z01), so2)));
                        acc[mt][nt][1] = __uint_as_float(
                            cvt2h(mul2(sin2_small(z23), so2)));
                    }
                }
                BAR_SYNC(barM, 128);         // readers of A done
#pragma unroll
                for (int mt = 0; mt < 2; mt++) {
                    int pr = mw * 32 + mt * 16 + (l >> 2);
#pragma unroll
                    for (int nt = 0; nt < 8; nt++) {
                        int nc = nw * 64 + nt * 8 + (l & 3) * 2;
                        *(uint32_t*)(smem + pr * AROWB + nc * 2) =
                            __float_as_uint(acc[mt][nt][0]);
                        *(uint32_t*)(smem + (pr + 8) * AROWB + nc * 2) =
                            __float_as_uint(acc[mt][nt][1]);
                    }
                }
                BAR_SYNC(barM, 128);         // new A visible
                // re-zero accumulators
#pragma unroll
                for (int mt = 0; mt < 2; mt++)
#pragma unroll
                    for (int nt = 0; nt < 8; nt++)
#pragma unroll
                        for (int q = 0; q < 4; q++) acc[mt][nt][q] = 0.0f;
            } else {
                // final: h3 = sin(y/512 + b3); partial out dots
                const ull is2 = pack2f(1.0f/512.0f, 1.0f/512.0f);
#pragma unroll
                for (int mt = 0; mt < 2; mt++)
#pragma unroll
                for (int nt = 0; nt < 8; nt++) {
                    int nc = nw * 64 + nt * 8 + (l & 3) * 2;
                    float2 bp = __ldg(reinterpret_cast<const float2*>(b3 + nc));
                    ull b2p = pack2f(bp.x, bp.y);
                    ull z01 = fma2(pack2f(acc[mt][nt][0], acc[mt][nt][1]),
                                   is2, b2p);
                    ull z23 = fma2(pack2f(acc[mt][nt][2], acc[mt][nt][3]),
                                   is2, b2p);
                    float h0, h1, h2, h3v;
                    unpack2f(sin2_small(z01), h0, h1);
                    unpack2f(sin2_small(z23), h2, h3v);
#pragma unroll
                    for (int cc = 0; cc < 3; cc++) {
                        float2 wp = __ldg(reinterpret_cast<const float2*>(
                            W4 + cc * HID + nc));
                        part[mt][0][cc] = fmaf(wp.x, h0,
                                          fmaf(wp.y, h1, part[mt][0][cc]));
                        part[mt][1][cc] = fmaf(wp.x, h2,
                                          fmaf(wp.y, h3v, part[mt][1][cc]));
                    }
                }
            }
        }
    }

    // ---- reduce + store ----
#pragma unroll
    for (int mt = 0; mt < 2; mt++)
#pragma unroll
    for (int rh = 0; rh < 2; rh++)
#pragma unroll
    for (int cc = 0; cc < 3; cc++) {
        float v = part[mt][rh][cc];
        v += __shfl_xor_sync(0xffffffffu, v, 1);
        v += __shfl_xor_sync(0xffffffffu, v, 2);
        part[mt][rh][cc] = v;
    }
    if ((l & 3) == 0) {
#pragma unroll
        for (int mt = 0; mt < 2; mt++)
#pragma unroll
        for (int rh = 0; rh < 2; rh++) {
            int p = mw * 32 + mt * 16 + rh * 8 + (l >> 2);
#pragma unroll
            for (int cc = 0; cc < 3; cc++)
                psum[nw * 192 + p * 3 + cc] = part[mt][rh][cc];
        }
    }

    __syncthreads();
    if (tid < PTILE * 3) {
        float v = psum[tid] + psum[192 + tid] + psum[384 + tid]
                + psum[576 + tid] + __ldg(b4 + tid % 3);
        int idx = tile0 * 3 + tid;
        if (idx < npts * 3) out[idx] = v;
    }
}

extern "C" void kernel_launch(void* const* d_in, const int* in_sizes, int n_in,
                              void* d_out, int out_size) {
    const float* x  = (const float*)d_in[0];
    const float* W0 = (const float*)d_in[1];
    const float* b0 = (const float*)d_in[2];
    const float* W1 = (const float*)d_in[3];
    const float* b1 = (const float*)d_in[4];
    const float* W2 = (const float*)d_in[5];
    const float* b2 = (const float*)d_in[6];
    const float* W3 = (const float*)d_in[7];
    const float* b3 = (const float*)d_in[8];
    const float* W4 = (const float*)d_in[9];
    const float* b4 = (const float*)d_in[10];
    float* out = (float*)d_out;

    int npts = in_sizes[0] / 3;
    int nblocks = (npts + PTILE - 1) / PTILE;

    siren_prep_kernel<<<384, 256>>>(W0, b0, W1, W2, W3);

    cudaFuncSetAttribute(siren_mma_kernel,
                         cudaFuncAttributeMaxDynamicSharedMemorySize, SMEM_SZ);
    siren_mma_kernel<<<nblocks, NTHREADS, SMEM_SZ>>>(
        x, b1, b2, b3, W4, b4, out, npts);
}